// round 1
// baseline (speedup 1.0000x reference)
#include <cuda_runtime.h>
#include <cuda_bf16.h>

// Problem dims (compile-time)
#define LL 1024
#define HH 2048
#define DDI 4096
#define NSS 16
#define RR 128
#define KCC 4

// ---------------- scratch buffers (allocation-free: __device__ globals) ----------------
__device__ float g_hs_pre[DDI * LL];   // pre-conv states [d, l]
__device__ float g_gate  [DDI * LL];   // gate projection [d, l]
__device__ float g_hs    [DDI * LL];   // post conv+silu  [d, l]
__device__ float g_ts    [LL * RR];    // time_step       [l, r]
__device__ float g_dt    [DDI * LL];   // softplus dt     [d, l]  (transposed store)
__device__ float g_Bm    [LL * NSS];   // B               [l, n]
__device__ float g_Cm    [LL * NSS];   // C               [l, n]
__device__ float g_y     [DDI * LL];   // gated ssm out   [d, l]

// ---------------- device math helpers ----------------
__device__ __forceinline__ float softplusf(float x) {
    return (x > 20.f) ? x : log1pf(expf(x));
}
__device__ __forceinline__ float siluf(float v) {
    return v / (1.f + expf(-v));
}

// ---------------- generic strided fp32 GEMM ----------------
// C[m*ldc_m + n*ldc_n] = epi( sum_k A[m*lda_m + k*lda_k] * B[n*ldb_n + k*ldb_k] )
// EPI==0: plain store. EPI==1: softplus(acc + bias[n]).
// A_KC / B_KC: whether the k-stride is 1 (selects the coalesced smem-load mapping).
template<int BM, int BN, int BK, int TM, int TN, bool A_KC, bool B_KC, int EPI>
__global__ void gemm_f32_kernel(const float* __restrict__ A, const float* __restrict__ B,
                                float* __restrict__ Cp, const float* __restrict__ bias,
                                int M, int N, int K,
                                int lda_m, int lda_k, int ldb_n, int ldb_k,
                                int ldc_m, int ldc_n)
{
    __shared__ float As[BK][BM];
    __shared__ float Bs[BK][BN];
    constexpr int THREADS = (BM / TM) * (BN / TN);
    const int tid = threadIdx.x;
    const int tx = tid % (BN / TN);
    const int ty = tid / (BN / TN);
    const int m0 = blockIdx.y * BM;
    const int n0 = blockIdx.x * BN;

    float acc[TM][TN];
#pragma unroll
    for (int i = 0; i < TM; i++)
#pragma unroll
        for (int j = 0; j < TN; j++) acc[i][j] = 0.f;

    for (int k0 = 0; k0 < K; k0 += BK) {
        // load A tile
#pragma unroll 4
        for (int i = tid; i < BM * BK; i += THREADS) {
            int m, k;
            if (A_KC) { m = i / BK; k = i % BK; }
            else      { k = i / BM; m = i % BM; }
            int gm = m0 + m, gk = k0 + k;
            As[k][m] = (gm < M) ? A[gm * lda_m + gk * lda_k] : 0.f;
        }
        // load B tile
#pragma unroll 4
        for (int i = tid; i < BN * BK; i += THREADS) {
            int n, k;
            if (B_KC) { n = i / BK; k = i % BK; }
            else      { k = i / BN; n = i % BN; }
            int gn = n0 + n, gk = k0 + k;
            Bs[k][n] = (gn < N) ? B[gn * ldb_n + gk * ldb_k] : 0.f;
        }
        __syncthreads();

#pragma unroll
        for (int k = 0; k < BK; k++) {
            float a[TM], b[TN];
#pragma unroll
            for (int i = 0; i < TM; i++) a[i] = As[k][ty * TM + i];
#pragma unroll
            for (int j = 0; j < TN; j++) b[j] = Bs[k][tx * TN + j];
#pragma unroll
            for (int i = 0; i < TM; i++)
#pragma unroll
                for (int j = 0; j < TN; j++)
                    acc[i][j] = fmaf(a[i], b[j], acc[i][j]);
        }
        __syncthreads();
    }

#pragma unroll
    for (int i = 0; i < TM; i++) {
        int gm = m0 + ty * TM + i;
        if (gm >= M) continue;
#pragma unroll
        for (int j = 0; j < TN; j++) {
            int gn = n0 + tx * TN + j;
            if (gn >= N) continue;
            float v = acc[i][j];
            if (EPI == 1) v = softplusf(v + bias[gn]);
            Cp[gm * ldc_m + gn * ldc_n] = v;
        }
    }
}

// ---------------- causal depthwise conv (K=4) + SiLU ----------------
__global__ void conv_silu_kernel(const float* __restrict__ conv_w,
                                 const float* __restrict__ conv_b)
{
    int idx = blockIdx.x * blockDim.x + threadIdx.x;
    if (idx >= DDI * LL) return;
    int d = idx / LL;
    int l = idx % LL;
    float acc = conv_b[d];
#pragma unroll
    for (int j = 0; j < KCC; j++) {
        int li = l - (KCC - 1) + j;
        if (li >= 0) acc = fmaf(conv_w[d * KCC + j], g_hs_pre[d * LL + li], acc);
    }
    g_hs[idx] = siluf(acc);
}

// ---------------- selective scan ----------------
// One warp handles 2 channels d; lanes [0..15] are states of channel d0,
// lanes [16..31] states of channel d1. 16-lane butterfly reduces over N.
// Fused epilogue: y = (sum_n h*C + hs*D) * silu(gate)
__global__ void scan_kernel(const float* __restrict__ A_log,
                            const float* __restrict__ Dv)
{
    int gwarp = (blockIdx.x * blockDim.x + threadIdx.x) >> 5;
    int lane  = threadIdx.x & 31;
    int c = lane >> 4;          // which channel within the warp
    int n = lane & 15;          // state index
    int d = gwarp * 2 + c;
    if (d >= DDI) return;

    const float Acoef = -__expf(A_log[d * NSS + n]);
    const float Dd = Dv[d];
    const float* dt_row   = g_dt   + d * LL;
    const float* hs_row   = g_hs   + d * LL;
    const float* gate_row = g_gate + d * LL;
    float* y_row = g_y + d * LL;

    float s = 0.f;
#pragma unroll 4
    for (int l = 0; l < LL; l++) {
        float dtv = dt_row[l];
        float hsv = hs_row[l];
        float Bv = g_Bm[l * NSS + n];
        float Cv = g_Cm[l * NSS + n];
        float a = __expf(Acoef * dtv);
        s = fmaf(a, s, dtv * Bv * hsv);
        float v = s * Cv;
        v += __shfl_xor_sync(0xFFFFFFFFu, v, 1);
        v += __shfl_xor_sync(0xFFFFFFFFu, v, 2);
        v += __shfl_xor_sync(0xFFFFFFFFu, v, 4);
        v += __shfl_xor_sync(0xFFFFFFFFu, v, 8);
        if (n == 0) {
            float gv = gate_row[l];
            y_row[l] = (v + hsv * Dd) * (gv / (1.f + __expf(-gv)));
        }
    }
}

// ---------------- host launcher ----------------
extern "C" void kernel_launch(void* const* d_in, const int* in_sizes, int n_in,
                              void* d_out, int out_size)
{
    const float* x           = (const float*)d_in[0];   // [B,L,H]
    const float* W_in_states = (const float*)d_in[1];   // [DI,H]
    const float* W_in_gates  = (const float*)d_in[2];   // [DI,H]
    const float* conv_w      = (const float*)d_in[3];   // [DI,K]
    const float* conv_b      = (const float*)d_in[4];   // [DI]
    const float* W_dt        = (const float*)d_in[5];   // [R,DI]
    const float* W_b         = (const float*)d_in[6];   // [N,DI]
    const float* W_c         = (const float*)d_in[7];   // [N,DI]
    const float* W_dtproj    = (const float*)d_in[8];   // [DI,R]
    const float* b_dtproj    = (const float*)d_in[9];   // [DI]
    const float* A_log       = (const float*)d_in[10];  // [DI,N]
    const float* Dv          = (const float*)d_in[11];  // [DI]
    const float* W_out       = (const float*)d_in[12];  // [H,DI]
    float* out = (float*)d_out;                          // [B,L,H]

    float *hs_pre, *gate, *hs, *ts, *dt, *Bm, *Cm, *y;
    cudaGetSymbolAddress((void**)&hs_pre, g_hs_pre);
    cudaGetSymbolAddress((void**)&gate,   g_gate);
    cudaGetSymbolAddress((void**)&hs,     g_hs);
    cudaGetSymbolAddress((void**)&ts,     g_ts);
    cudaGetSymbolAddress((void**)&dt,     g_dt);
    cudaGetSymbolAddress((void**)&Bm,     g_Bm);
    cudaGetSymbolAddress((void**)&Cm,     g_Cm);
    cudaGetSymbolAddress((void**)&y,      g_y);

    // G1: hs_pre[d,l] = W_in_states[d,:] . x[l,:]   (M=DI, N=L, K=H)
    {
        dim3 grid(LL / 128, DDI / 128);
        gemm_f32_kernel<128,128,16,8,8,true,true,0><<<grid, 256>>>(
            W_in_states, x, hs_pre, nullptr,
            DDI, LL, HH, HH, 1, HH, 1, LL, 1);
    }
    // G2: gate[d,l]
    {
        dim3 grid(LL / 128, DDI / 128);
        gemm_f32_kernel<128,128,16,8,8,true,true,0><<<grid, 256>>>(
            W_in_gates, x, gate, nullptr,
            DDI, LL, HH, HH, 1, HH, 1, LL, 1);
    }
    // conv + silu -> hs[d,l]
    conv_silu_kernel<<<(DDI * LL) / 256, 256>>>(conv_w, conv_b);

    // G3: ts[l,r] = hs^T . W_dt^T   (M=L, N=R, K=DI); A[m,k]=hs[k*L+m]
    {
        dim3 grid(RR / 128, LL / 128);
        gemm_f32_kernel<128,128,16,8,8,false,true,0><<<grid, 256>>>(
            hs, W_dt, ts, nullptr,
            LL, RR, DDI, 1, LL, DDI, 1, RR, 1);
    }
    // G4: dt[d,l] = softplus(ts . W_dtproj^T + b)  (M=L, N=DI, K=R), transposed store
    {
        dim3 grid(DDI / 128, LL / 128);
        gemm_f32_kernel<128,128,16,8,8,true,true,1><<<grid, 256>>>(
            ts, W_dtproj, dt, b_dtproj,
            LL, DDI, RR, RR, 1, RR, 1, 1, LL);
    }
    // G5a: Bm[l,n]  (M=L, N=16, K=DI)
    {
        dim3 grid(1, LL / 128);
        gemm_f32_kernel<128,16,16,8,1,false,true,0><<<grid, 256>>>(
            hs, W_b, Bm, nullptr,
            LL, NSS, DDI, 1, LL, DDI, 1, NSS, 1);
    }
    // G5b: Cm[l,n]
    {
        dim3 grid(1, LL / 128);
        gemm_f32_kernel<128,16,16,8,1,false,true,0><<<grid, 256>>>(
            hs, W_c, Cm, nullptr,
            LL, NSS, DDI, 1, LL, DDI, 1, NSS, 1);
    }
    // selective scan + gating -> y[d,l]
    {
        int warps = DDI / 2;               // 2048 warps
        int threads = 256;
        int blocks = (warps * 32) / threads;
        scan_kernel<<<blocks, threads>>>(A_log, Dv);
    }
    // G6: out[l,o] = y^T . W_out^T   (M=L, N=H, K=DI); A[m,k]=y[k*L+m]
    {
        dim3 grid(HH / 128, LL / 128);
        gemm_f32_kernel<128,128,16,8,8,false,true,0><<<grid, 256>>>(
            y, W_out, out, nullptr,
            LL, HH, DDI, 1, LL, DDI, 1, HH, 1);
    }
}

// round 3
// speedup vs baseline: 2.8243x; 2.8243x over previous
#include <cuda_runtime.h>
#include <cstdint>

#define LL 1024
#define HH 2048
#define DDI 4096
#define NSS 16
#define RR 128

// ---------------- scratch ([L, ...] row-major, K-contiguous for GEMMs) ----------------
__device__ float g_hs_pre[LL * DDI];
__device__ float g_gate  [LL * DDI];
__device__ float g_hs    [LL * DDI];
__device__ float g_ts    [LL * RR];
__device__ float g_dt    [LL * DDI];
__device__ float g_BC    [LL * 32];
__device__ float g_y     [LL * DDI];
// tf32-rounded copies of GEMM operands
__device__ float g_xr  [LL * HH];
__device__ float g_wis [DDI * HH];
__device__ float g_wig [DDI * HH];
__device__ float g_wout[HH * DDI];
__device__ float g_wdt [RR * DDI];
__device__ float g_wdtp[DDI * RR];
__device__ float g_wbc [32 * DDI];

// ---------------- helpers ----------------
__device__ __forceinline__ uint32_t smem_u32(const void* p) {
    uint32_t a;
    asm("{ .reg .u64 t; cvta.to.shared.u64 t, %1; cvt.u32.u64 %0, t; }" : "=r"(a) : "l"(p));
    return a;
}
__device__ __forceinline__ void cp_async16(uint32_t dst, const void* src, bool pred) {
    int bytes = pred ? 16 : 0;
    asm volatile("cp.async.cg.shared.global [%0], [%1], 16, %2;" :: "r"(dst), "l"(src), "r"(bytes));
}
#define CP_COMMIT() asm volatile("cp.async.commit_group;" ::: "memory")
#define CP_WAIT1()  asm volatile("cp.async.wait_group 1;" ::: "memory")
#define CP_WAIT0()  asm volatile("cp.async.wait_group 0;" ::: "memory")

__device__ __forceinline__ float softplusf(float x) {
    return (x > 20.f) ? x : log1pf(expf(x));
}
__device__ __forceinline__ float rtf32(float x) {
    uint32_t u;
    asm("cvt.rna.tf32.f32 %0, %1;" : "=r"(u) : "f"(x));
    return __uint_as_float(u);
}
__device__ __forceinline__ void mma_tf32(float* c, const uint32_t* a, const uint32_t* b) {
    asm volatile(
        "mma.sync.aligned.m16n8k8.row.col.f32.tf32.tf32.f32 "
        "{%0,%1,%2,%3}, {%4,%5,%6,%7}, {%8,%9}, {%0,%1,%2,%3};"
        : "+f"(c[0]), "+f"(c[1]), "+f"(c[2]), "+f"(c[3])
        : "r"(a[0]), "r"(a[1]), "r"(a[2]), "r"(a[3]), "r"(b[0]), "r"(b[1]));
}

// ---------------- tf32 mma.sync GEMM: C[M,N] = A[M,K] . B[N,K]^T ----------------
// Row strides of A and B equal K. EPI: 0 plain, 1 softplus(acc+bias[n]), 2 tf32-round.
// BM=128, BN=128, BK=32, 256 threads, warp grid 2(M) x 4(N), warp tile 64x32.
#define SAPAD 36
#define STAGE_F (2 * 128 * SAPAD)   // floats per stage (A tile + B tile)

template<int EPI>
__global__ __launch_bounds__(256, 2) void gemm_mma(
    const float* __restrict__ A, const float* __restrict__ B, float* __restrict__ C,
    const float* __restrict__ bias, int M, int N, int K, int ldc)
{
    extern __shared__ float smem[];
    const int tid = threadIdx.x;
    const int wid = tid >> 5;
    const int lane = tid & 31;
    const int m0 = blockIdx.y * 128;
    const int n0 = blockIdx.x * 128;
    const int KT = K >> 5;

    const int wm = (wid >> 2) * 64;   // warp M offset in tile
    const int wn = (wid & 3) * 32;    // warp N offset in tile

    float acc[4][4][4];
#pragma unroll
    for (int i = 0; i < 4; i++)
#pragma unroll
        for (int j = 0; j < 4; j++)
#pragma unroll
            for (int r = 0; r < 4; r++) acc[i][j][r] = 0.f;

    const uint32_t smem_b = smem_u32(smem);

    auto load_tile = [&](int kt, int s) {
        const uint32_t a_s = smem_b + (uint32_t)(s * STAGE_F) * 4u;
        const uint32_t b_s = a_s + 128u * SAPAD * 4u;
        const int k0 = kt << 5;
        const float* Ab = A + (size_t)m0 * K + k0;
        const float* Bb = B + (size_t)n0 * K + k0;
#pragma unroll
        for (int i = 0; i < 4; i++) {
            int idx = tid + i * 256;
            int row = idx >> 3;
            int ch = (idx & 7) << 2;             // float offset within row
            cp_async16(a_s + (uint32_t)(row * SAPAD + ch) * 4u, Ab + (size_t)row * K + ch, true);
        }
#pragma unroll
        for (int i = 0; i < 4; i++) {
            int idx = tid + i * 256;
            int row = idx >> 3;
            int ch = (idx & 7) << 2;
            cp_async16(b_s + (uint32_t)(row * SAPAD + ch) * 4u, Bb + (size_t)row * K + ch,
                       (n0 + row) < N);
        }
        CP_COMMIT();
    };

    load_tile(0, 0);

    for (int kt = 0; kt < KT; kt++) {
        if (kt + 1 < KT) {
            load_tile(kt + 1, (kt + 1) & 1);
            CP_WAIT1();
        } else {
            CP_WAIT0();
        }
        __syncthreads();

        const float* As_ = smem + (kt & 1) * STAGE_F;
        const float* Bs_ = As_ + 128 * SAPAD;
        const int ar = lane >> 2;
        const int ac = lane & 3;

#pragma unroll
        for (int ks = 0; ks < 4; ks++) {
            const int k0 = ks << 3;
            uint32_t af[4][4];
            uint32_t bf[4][2];
#pragma unroll
            for (int mt = 0; mt < 4; mt++) {
                int r = wm + mt * 16 + ar;
                const float* p0 = As_ + r * SAPAD + k0 + ac;
                const float* p1 = As_ + (r + 8) * SAPAD + k0 + ac;
                af[mt][0] = __float_as_uint(p0[0]);
                af[mt][1] = __float_as_uint(p1[0]);
                af[mt][2] = __float_as_uint(p0[4]);
                af[mt][3] = __float_as_uint(p1[4]);
            }
#pragma unroll
            for (int nt = 0; nt < 4; nt++) {
                int n = wn + nt * 8 + ar;
                const float* p = Bs_ + n * SAPAD + k0 + ac;
                bf[nt][0] = __float_as_uint(p[0]);
                bf[nt][1] = __float_as_uint(p[4]);
            }
#pragma unroll
            for (int mt = 0; mt < 4; mt++)
#pragma unroll
                for (int nt = 0; nt < 4; nt++)
                    mma_tf32(acc[mt][nt], af[mt], bf[nt]);
        }
        __syncthreads();
    }

    // epilogue
    const int ar = lane >> 2;
    const int ac = lane & 3;
#pragma unroll
    for (int mt = 0; mt < 4; mt++) {
#pragma unroll
        for (int nt = 0; nt < 4; nt++) {
            int row = m0 + wm + mt * 16 + ar;
            int col = n0 + wn + nt * 8 + ac * 2;
            if (col >= N) continue;
            float* c0 = C + (size_t)row * ldc + col;
            float* c1 = C + (size_t)(row + 8) * ldc + col;
            float v0 = acc[mt][nt][0], v1 = acc[mt][nt][1];
            float v2 = acc[mt][nt][2], v3 = acc[mt][nt][3];
            if (EPI == 1) {
                float b0 = bias[col], b1 = bias[col + 1];
                v0 = softplusf(v0 + b0); v1 = softplusf(v1 + b1);
                v2 = softplusf(v2 + b0); v3 = softplusf(v3 + b1);
            } else if (EPI == 2) {
                v0 = rtf32(v0); v1 = rtf32(v1); v2 = rtf32(v2); v3 = rtf32(v3);
            }
            *(float2*)c0 = make_float2(v0, v1);
            *(float2*)c1 = make_float2(v2, v3);
        }
    }
}

// ---------------- round-to-tf32 copy ----------------
__global__ void round_copy(const float4* __restrict__ in, float4* __restrict__ out, int n4) {
    int i = blockIdx.x * blockDim.x + threadIdx.x;
    if (i < n4) {
        float4 v = in[i];
        v.x = rtf32(v.x); v.y = rtf32(v.y); v.z = rtf32(v.z); v.w = rtf32(v.w);
        out[i] = v;
    }
}

// ---------------- conv (K=4, causal) + SiLU, [L, DI] layout ----------------
__global__ void conv_silu_kernel(const float* __restrict__ cw, const float* __restrict__ cb) {
    int idx = blockIdx.x * blockDim.x + threadIdx.x;
    int l = idx >> 12;
    int d = idx & (DDI - 1);
    float4 w = ((const float4*)cw)[d];
    float acc = cb[d];
    const float* hp = g_hs_pre + d;
    if (l >= 3) acc = fmaf(w.x, hp[(size_t)(l - 3) * DDI], acc);
    if (l >= 2) acc = fmaf(w.y, hp[(size_t)(l - 2) * DDI], acc);
    if (l >= 1) acc = fmaf(w.z, hp[(size_t)(l - 1) * DDI], acc);
    acc = fmaf(w.w, hp[(size_t)l * DDI], acc);
    float s = acc / (1.f + __expf(-acc));
    g_hs[idx] = rtf32(s);
}

// ---------------- selective scan (warp = 2 channels, lane = state) ----------------
__global__ void scan_kernel(const float* __restrict__ A_log, const float* __restrict__ Dv) {
    int gwarp = (blockIdx.x * blockDim.x + threadIdx.x) >> 5;
    int lane = threadIdx.x & 31;
    int c = lane >> 4;
    int n = lane & 15;
    int d = gwarp * 2 + c;

    const float Acoef = -__expf(A_log[d * NSS + n]);
    const float Dd = Dv[d];
    float s = 0.f;
#pragma unroll 2
    for (int l = 0; l < LL; l++) {
        float dtv = g_dt[(size_t)l * DDI + d];
        float hsv = g_hs[(size_t)l * DDI + d];
        float Bv = g_BC[l * 32 + n];
        float Cv = g_BC[l * 32 + 16 + n];
        float a = __expf(Acoef * dtv);
        s = fmaf(a, s, dtv * Bv * hsv);
        float v = s * Cv;
        v += __shfl_xor_sync(0xFFFFFFFFu, v, 1);
        v += __shfl_xor_sync(0xFFFFFFFFu, v, 2);
        v += __shfl_xor_sync(0xFFFFFFFFu, v, 4);
        v += __shfl_xor_sync(0xFFFFFFFFu, v, 8);
        if (n == 0) {
            float gv = g_gate[(size_t)l * DDI + d];
            float y = (v + hsv * Dd) * (gv / (1.f + __expf(-gv)));
            g_y[(size_t)l * DDI + d] = rtf32(y);
        }
    }
}

// ---------------- host ----------------
extern "C" void kernel_launch(void* const* d_in, const int* in_sizes, int n_in,
                              void* d_out, int out_size)
{
    const float* x           = (const float*)d_in[0];
    const float* W_in_states = (const float*)d_in[1];
    const float* W_in_gates  = (const float*)d_in[2];
    const float* conv_w      = (const float*)d_in[3];
    const float* conv_b      = (const float*)d_in[4];
    const float* W_dt        = (const float*)d_in[5];
    const float* W_b         = (const float*)d_in[6];
    const float* W_c         = (const float*)d_in[7];
    const float* W_dtproj    = (const float*)d_in[8];
    const float* b_dtproj    = (const float*)d_in[9];
    const float* A_log       = (const float*)d_in[10];
    const float* Dv          = (const float*)d_in[11];
    const float* W_out       = (const float*)d_in[12];
    float* out = (float*)d_out;

    float *hs_pre, *gate, *hs, *ts, *dt, *BC, *y;
    float *xr, *wis, *wig, *wout, *wdt, *wdtp, *wbc;
    cudaGetSymbolAddress((void**)&hs_pre, g_hs_pre);
    cudaGetSymbolAddress((void**)&gate,   g_gate);
    cudaGetSymbolAddress((void**)&hs,     g_hs);
    cudaGetSymbolAddress((void**)&ts,     g_ts);
    cudaGetSymbolAddress((void**)&dt,     g_dt);
    cudaGetSymbolAddress((void**)&BC,     g_BC);
    cudaGetSymbolAddress((void**)&y,      g_y);
    cudaGetSymbolAddress((void**)&xr,     g_xr);
    cudaGetSymbolAddress((void**)&wis,    g_wis);
    cudaGetSymbolAddress((void**)&wig,    g_wig);
    cudaGetSymbolAddress((void**)&wout,   g_wout);
    cudaGetSymbolAddress((void**)&wdt,    g_wdt);
    cudaGetSymbolAddress((void**)&wdtp,   g_wdtp);
    cudaGetSymbolAddress((void**)&wbc,    g_wbc);

    const int SMEM = 2 * STAGE_F * 4;   // 73728 bytes
    cudaFuncSetAttribute(gemm_mma<0>, cudaFuncAttributeMaxDynamicSharedMemorySize, SMEM);
    cudaFuncSetAttribute(gemm_mma<1>, cudaFuncAttributeMaxDynamicSharedMemorySize, SMEM);
    cudaFuncSetAttribute(gemm_mma<2>, cudaFuncAttributeMaxDynamicSharedMemorySize, SMEM);

    auto rc = [&](const float* src, float* dst, int n) {
        int n4 = n / 4;
        round_copy<<<(n4 + 255) / 256, 256>>>((const float4*)src, (float4*)dst, n4);
    };
    rc(x, xr, LL * HH);
    rc(W_in_states, wis, DDI * HH);
    rc(W_in_gates,  wig, DDI * HH);
    rc(W_out, wout, HH * DDI);
    rc(W_dt,  wdt,  RR * DDI);
    rc(W_dtproj, wdtp, DDI * RR);
    rc(W_b, wbc, NSS * DDI);
    rc(W_c, wbc + NSS * DDI, NSS * DDI);

    // G1: hs_pre[L,DI] = x . W_in_states^T
    gemm_mma<0><<<dim3(DDI / 128, LL / 128), 256, SMEM>>>(xr, wis, hs_pre, nullptr, LL, DDI, HH, DDI);
    // G2: gate[L,DI]
    gemm_mma<0><<<dim3(DDI / 128, LL / 128), 256, SMEM>>>(xr, wig, gate, nullptr, LL, DDI, HH, DDI);
    // conv + silu -> hs[L,DI] (tf32-rounded)
    conv_silu_kernel<<<(LL * DDI) / 256, 256>>>(conv_w, conv_b);
    // G3: ts[L,R] = hs . W_dt^T (rounded, feeds G4)
    gemm_mma<2><<<dim3(1, LL / 128), 256, SMEM>>>(hs, wdt, ts, nullptr, LL, RR, DDI, RR);
    // G4: dt[L,DI] = softplus(ts . W_dtproj^T + b)
    gemm_mma<1><<<dim3(DDI / 128, LL / 128), 256, SMEM>>>(ts, wdtp, dt, b_dtproj, LL, DDI, RR, DDI);
    // G5: BC[L,32] = hs . [W_b;W_c]^T
    gemm_mma<0><<<dim3(1, LL / 128), 256, SMEM>>>(hs, wbc, BC, nullptr, LL, 32, DDI, 32);
    // scan + gating -> y[L,DI]
    scan_kernel<<<(DDI / 2 * 32) / 256, 256>>>(A_log, Dv);
    // G6: out[L,H] = y . W_out^T
    gemm_mma<0><<<dim3(HH / 128, LL / 128), 256, SMEM>>>(y, wout, out, nullptr, LL, HH, DDI, HH);
}

// round 4
// speedup vs baseline: 3.4165x; 1.2097x over previous
#include <cuda_runtime.h>
#include <cstdint>

#define LL 1024
#define HH 2048
#define DDI 4096
#define NSS 16
#define RR 128

// ---------------- scratch ----------------
__device__ float g_pg   [LL * 2 * DDI];   // [l, 0:4096]=hs_pre, [l, 4096:8192]=gate
__device__ float g_hs   [LL * DDI];       // post conv+silu, tf32-rounded
__device__ float g_ts   [LL * RR];        // rounded time_step
__device__ float g_dt   [LL * DDI];       // softplus dt
__device__ float g_tsbc [LL * 160];       // split-K accumulator: ts(128) | B(16) | C(16)
__device__ float g_y    [LL * DDI];
// tf32-rounded GEMM operands
__device__ float g_xr   [LL * HH];
__device__ float g_w12  [2 * DDI * HH];   // W_in_states ; W_in_gates
__device__ float g_wout [HH * DDI];
__device__ float g_wdtbc[160 * DDI];      // W_dt(128) ; W_b(16) ; W_c(16)
__device__ float g_wdtp [DDI * RR];

// ---------------- helpers ----------------
__device__ __forceinline__ uint32_t smem_u32(const void* p) {
    uint32_t a;
    asm("{ .reg .u64 t; cvta.to.shared.u64 t, %1; cvt.u32.u64 %0, t; }" : "=r"(a) : "l"(p));
    return a;
}
__device__ __forceinline__ void cp_async16(uint32_t dst, const void* src, bool pred) {
    int bytes = pred ? 16 : 0;
    asm volatile("cp.async.cg.shared.global [%0], [%1], 16, %2;" :: "r"(dst), "l"(src), "r"(bytes));
}
#define CP_COMMIT() asm volatile("cp.async.commit_group;" ::: "memory")
#define CP_WAIT1()  asm volatile("cp.async.wait_group 1;" ::: "memory")
#define CP_WAIT0()  asm volatile("cp.async.wait_group 0;" ::: "memory")

__device__ __forceinline__ float softplusf(float x) {
    return (x > 20.f) ? x : log1pf(expf(x));
}
__device__ __forceinline__ float rtf32(float x) {
    uint32_t u;
    asm("cvt.rna.tf32.f32 %0, %1;" : "=r"(u) : "f"(x));
    return __uint_as_float(u);
}
__device__ __forceinline__ void mma_tf32(float* c, const uint32_t* a, const uint32_t* b) {
    asm volatile(
        "mma.sync.aligned.m16n8k8.row.col.f32.tf32.tf32.f32 "
        "{%0,%1,%2,%3}, {%4,%5,%6,%7}, {%8,%9}, {%0,%1,%2,%3};"
        : "+f"(c[0]), "+f"(c[1]), "+f"(c[2]), "+f"(c[3])
        : "r"(a[0]), "r"(a[1]), "r"(a[2]), "r"(a[3]), "r"(b[0]), "r"(b[1]));
}
#define LDSM_X4(r0, r1, r2, r3, addr) \
    asm volatile("ldmatrix.sync.aligned.m8n8.x4.shared.b16 {%0,%1,%2,%3}, [%4];" \
                 : "=r"(r0), "=r"(r1), "=r"(r2), "=r"(r3) : "r"(addr))
#define LDSM_X2(r0, r1, addr) \
    asm volatile("ldmatrix.sync.aligned.m8n8.x2.shared.b16 {%0,%1}, [%2];" \
                 : "=r"(r0), "=r"(r1) : "r"(addr))

// ---------------- tf32 mma.sync GEMM: C[M,N] = A[M,K] . B[N,K]^T ----------------
// EPI: 0 plain, 1 softplus(acc+bias[n]), 3 atomicAdd (split-K over gridDim.z)
#define SAPAD 36
#define STAGE_F (2 * 128 * SAPAD)
#define STAGE_BYTES (STAGE_F * 4)

template<int EPI>
__global__ __launch_bounds__(256, 2) void gemm_mma(
    const float* __restrict__ A, const float* __restrict__ B, float* __restrict__ C,
    const float* __restrict__ bias, int M, int N, int K, int ldc)
{
    extern __shared__ float smem[];
    const int tid = threadIdx.x;
    const int wid = tid >> 5;
    const int lane = tid & 31;
    const int m0 = blockIdx.y * 128;
    const int n0 = blockIdx.x * 128;
    const int Ksplit = K / gridDim.z;
    const int kbase = blockIdx.z * Ksplit;
    const int KT = Ksplit >> 5;

    const int wm = (wid >> 2) * 64;
    const int wn = (wid & 3) * 32;

    float acc[4][4][4];
#pragma unroll
    for (int i = 0; i < 4; i++)
#pragma unroll
        for (int j = 0; j < 4; j++)
#pragma unroll
            for (int r = 0; r < 4; r++) acc[i][j][r] = 0.f;

    const uint32_t smem_b = smem_u32(smem);

    // per-lane ldmatrix byte offsets within a stage
    uint32_t aoff[4], boff[4];
    {
        const int arow = lane & 15;
        const int acolw = (lane >> 4) * 4;
#pragma unroll
        for (int mt = 0; mt < 4; mt++)
            aoff[mt] = (uint32_t)(((wm + mt * 16 + arow) * SAPAD + acolw) * 4);
        const int brow = lane & 7;
        const int bcolw = ((lane >> 3) & 1) * 4;
#pragma unroll
        for (int nt = 0; nt < 4; nt++)
            boff[nt] = (uint32_t)((128 * SAPAD + (wn + nt * 8 + brow) * SAPAD + bcolw) * 4);
    }

    auto load_tile = [&](int kt, int s) {
        const uint32_t a_s = smem_b + (uint32_t)(s * STAGE_BYTES);
        const uint32_t b_s = a_s + 128u * SAPAD * 4u;
        const int k0 = kbase + (kt << 5);
        const float* Ab = A + (size_t)m0 * K + k0;
        const float* Bb = B + (size_t)n0 * K + k0;
#pragma unroll
        for (int i = 0; i < 4; i++) {
            int idx = tid + i * 256;
            int row = idx >> 3;
            int ch = (idx & 7) << 2;
            cp_async16(a_s + (uint32_t)(row * SAPAD + ch) * 4u, Ab + (size_t)row * K + ch, true);
        }
#pragma unroll
        for (int i = 0; i < 4; i++) {
            int idx = tid + i * 256;
            int row = idx >> 3;
            int ch = (idx & 7) << 2;
            cp_async16(b_s + (uint32_t)(row * SAPAD + ch) * 4u, Bb + (size_t)row * K + ch,
                       (n0 + row) < N);
        }
        CP_COMMIT();
    };

    load_tile(0, 0);

    for (int kt = 0; kt < KT; kt++) {
        if (kt + 1 < KT) {
            load_tile(kt + 1, (kt + 1) & 1);
            CP_WAIT1();
        } else {
            CP_WAIT0();
        }
        __syncthreads();

        const uint32_t stage = smem_b + (uint32_t)((kt & 1) * STAGE_BYTES);
#pragma unroll
        for (int ks = 0; ks < 4; ks++) {
            uint32_t af[4][4], bf[4][2];
#pragma unroll
            for (int mt = 0; mt < 4; mt++)
                LDSM_X4(af[mt][0], af[mt][1], af[mt][2], af[mt][3],
                        stage + aoff[mt] + (uint32_t)(ks * 32));
#pragma unroll
            for (int nt = 0; nt < 4; nt++)
                LDSM_X2(bf[nt][0], bf[nt][1], stage + boff[nt] + (uint32_t)(ks * 32));
#pragma unroll
            for (int mt = 0; mt < 4; mt++)
#pragma unroll
                for (int nt = 0; nt < 4; nt++)
                    mma_tf32(acc[mt][nt], af[mt], bf[nt]);
        }
        __syncthreads();
    }

    // epilogue
    const int ar = lane >> 2;
    const int ac = lane & 3;
#pragma unroll
    for (int mt = 0; mt < 4; mt++) {
#pragma unroll
        for (int nt = 0; nt < 4; nt++) {
            int row = m0 + wm + mt * 16 + ar;
            int col = n0 + wn + nt * 8 + ac * 2;
            if (col >= N) continue;
            float* c0 = C + (size_t)row * ldc + col;
            float* c1 = C + (size_t)(row + 8) * ldc + col;
            float v0 = acc[mt][nt][0], v1 = acc[mt][nt][1];
            float v2 = acc[mt][nt][2], v3 = acc[mt][nt][3];
            if (EPI == 1) {
                float b0 = bias[col], b1 = bias[col + 1];
                v0 = softplusf(v0 + b0); v1 = softplusf(v1 + b1);
                v2 = softplusf(v2 + b0); v3 = softplusf(v3 + b1);
            }
            if (EPI == 3) {
                atomicAdd(c0, v0); atomicAdd(c0 + 1, v1);
                atomicAdd(c1, v2); atomicAdd(c1 + 1, v3);
            } else {
                *(float2*)c0 = make_float2(v0, v1);
                *(float2*)c1 = make_float2(v2, v3);
            }
        }
    }
}

// ---------------- small kernels ----------------
__global__ void round_copy(const float4* __restrict__ in, float4* __restrict__ out, int n4) {
    int i = blockIdx.x * blockDim.x + threadIdx.x;
    if (i < n4) {
        float4 v = in[i];
        v.x = rtf32(v.x); v.y = rtf32(v.y); v.z = rtf32(v.z); v.w = rtf32(v.w);
        out[i] = v;
    }
}
__global__ void zero_kernel(float* __restrict__ p, int n) {
    int i = blockIdx.x * blockDim.x + threadIdx.x;
    if (i < n) p[i] = 0.f;
}
__global__ void round_ts_kernel() {
    int i = blockIdx.x * blockDim.x + threadIdx.x;   // i < LL*RR
    int l = i >> 7, r = i & 127;
    g_ts[i] = rtf32(g_tsbc[l * 160 + r]);
}

// conv (K=4, causal) + SiLU; input g_pg[:, 0:4096] (stride 8192), output g_hs (stride 4096)
__global__ void conv_silu_kernel(const float* __restrict__ cw, const float* __restrict__ cb) {
    int idx = blockIdx.x * blockDim.x + threadIdx.x;
    int l = idx >> 12;
    int d = idx & (DDI - 1);
    float4 w = ((const float4*)cw)[d];
    float acc = cb[d];
    const float* hp = g_pg + d;
    if (l >= 3) acc = fmaf(w.x, hp[(size_t)(l - 3) * 8192], acc);
    if (l >= 2) acc = fmaf(w.y, hp[(size_t)(l - 2) * 8192], acc);
    if (l >= 1) acc = fmaf(w.z, hp[(size_t)(l - 1) * 8192], acc);
    acc = fmaf(w.w, hp[(size_t)l * 8192], acc);
    float s = acc / (1.f + __expf(-acc));
    g_hs[idx] = rtf32(s);
}

// selective scan: warp = 2 channels, lane = state n
__global__ void scan_kernel(const float* __restrict__ A_log, const float* __restrict__ Dv) {
    int gwarp = (blockIdx.x * blockDim.x + threadIdx.x) >> 5;
    int lane = threadIdx.x & 31;
    int c = lane >> 4;
    int n = lane & 15;
    int d = gwarp * 2 + c;

    const float Acoef = -__expf(A_log[d * NSS + n]);
    const float Dd = Dv[d];
    float s = 0.f;
#pragma unroll 2
    for (int l = 0; l < LL; l++) {
        float dtv = g_dt[(size_t)l * DDI + d];
        float hsv = g_hs[(size_t)l * DDI + d];
        float Bv = g_tsbc[l * 160 + 128 + n];
        float Cv = g_tsbc[l * 160 + 144 + n];
        float a = __expf(Acoef * dtv);
        s = fmaf(a, s, dtv * Bv * hsv);
        float v = s * Cv;
        v += __shfl_xor_sync(0xFFFFFFFFu, v, 1);
        v += __shfl_xor_sync(0xFFFFFFFFu, v, 2);
        v += __shfl_xor_sync(0xFFFFFFFFu, v, 4);
        v += __shfl_xor_sync(0xFFFFFFFFu, v, 8);
        if (n == 0) {
            float gv = g_pg[(size_t)l * 8192 + 4096 + d];
            float y = (v + hsv * Dd) * (gv / (1.f + __expf(-gv)));
            g_y[(size_t)l * DDI + d] = rtf32(y);
        }
    }
}

// ---------------- host ----------------
extern "C" void kernel_launch(void* const* d_in, const int* in_sizes, int n_in,
                              void* d_out, int out_size)
{
    const float* x           = (const float*)d_in[0];
    const float* W_in_states = (const float*)d_in[1];
    const float* W_in_gates  = (const float*)d_in[2];
    const float* conv_w      = (const float*)d_in[3];
    const float* conv_b      = (const float*)d_in[4];
    const float* W_dt        = (const float*)d_in[5];
    const float* W_b         = (const float*)d_in[6];
    const float* W_c         = (const float*)d_in[7];
    const float* W_dtproj    = (const float*)d_in[8];
    const float* b_dtproj    = (const float*)d_in[9];
    const float* A_log       = (const float*)d_in[10];
    const float* Dv          = (const float*)d_in[11];
    const float* W_out       = (const float*)d_in[12];
    float* out = (float*)d_out;

    float *pg, *hs, *ts, *dt, *tsbc, *y, *xr, *w12, *wout, *wdtbc, *wdtp;
    cudaGetSymbolAddress((void**)&pg,    g_pg);
    cudaGetSymbolAddress((void**)&hs,    g_hs);
    cudaGetSymbolAddress((void**)&ts,    g_ts);
    cudaGetSymbolAddress((void**)&dt,    g_dt);
    cudaGetSymbolAddress((void**)&tsbc,  g_tsbc);
    cudaGetSymbolAddress((void**)&y,     g_y);
    cudaGetSymbolAddress((void**)&xr,    g_xr);
    cudaGetSymbolAddress((void**)&w12,   g_w12);
    cudaGetSymbolAddress((void**)&wout,  g_wout);
    cudaGetSymbolAddress((void**)&wdtbc, g_wdtbc);
    cudaGetSymbolAddress((void**)&wdtp,  g_wdtp);

    const int SMEM = 2 * STAGE_BYTES;   // 73728 bytes
    cudaFuncSetAttribute(gemm_mma<0>, cudaFuncAttributeMaxDynamicSharedMemorySize, SMEM);
    cudaFuncSetAttribute(gemm_mma<1>, cudaFuncAttributeMaxDynamicSharedMemorySize, SMEM);
    cudaFuncSetAttribute(gemm_mma<3>, cudaFuncAttributeMaxDynamicSharedMemorySize, SMEM);

    auto rc = [&](const float* src, float* dst, int n) {
        int n4 = n / 4;
        round_copy<<<(n4 + 255) / 256, 256>>>((const float4*)src, (float4*)dst, n4);
    };
    rc(x, xr, LL * HH);
    rc(W_in_states, w12, DDI * HH);
    rc(W_in_gates,  w12 + (size_t)DDI * HH, DDI * HH);
    rc(W_out, wout, HH * DDI);
    rc(W_dtproj, wdtp, DDI * RR);
    rc(W_dt, wdtbc, RR * DDI);
    rc(W_b, wdtbc + (size_t)RR * DDI, NSS * DDI);
    rc(W_c, wdtbc + (size_t)(RR + NSS) * DDI, NSS * DDI);
    zero_kernel<<<(LL * 160 + 255) / 256, 256>>>(tsbc, LL * 160);

    // G12: pg[L, 8192] = x . [W_in_states; W_in_gates]^T
    gemm_mma<0><<<dim3(64, 8), 256, SMEM>>>(xr, w12, pg, nullptr, LL, 2 * DDI, HH, 2 * DDI);
    // conv + silu -> hs[L, DI]
    conv_silu_kernel<<<(LL * DDI) / 256, 256>>>(conv_w, conv_b);
    // G35 (split-K=8, atomic): tsbc[L, 160] = hs . [W_dt; W_b; W_c]^T
    gemm_mma<3><<<dim3(2, 8, 8), 256, SMEM>>>(hs, wdtbc, tsbc, nullptr, LL, 160, DDI, 160);
    // round ts slice
    round_ts_kernel<<<(LL * RR) / 256, 256>>>();
    // G4: dt[L, DI] = softplus(ts . W_dtproj^T + b)
    gemm_mma<1><<<dim3(32, 8), 256, SMEM>>>(ts, wdtp, dt, b_dtproj, LL, DDI, RR, DDI);
    // scan + gating -> y[L, DI]
    scan_kernel<<<(DDI / 2 * 32) / 256, 256>>>(A_log, Dv);
    // G6: out[L, H] = y . W_out^T
    gemm_mma<0><<<dim3(16, 8), 256, SMEM>>>(y, wout, out, nullptr, LL, HH, DDI, HH);
}

// round 5
// speedup vs baseline: 3.4740x; 1.0168x over previous
#include <cuda_runtime.h>
#include <cstdint>

#define LL 1024
#define HH 2048
#define DDI 4096
#define NSS 16
#define RR 128

// ---------------- scratch ----------------
__device__ float g_pg   [LL * 2 * DDI];   // [l, 0:4096]=hs_pre, [l, 4096:8192]=gate
__device__ float g_hs   [LL * DDI];
__device__ float g_ts   [LL * RR];
__device__ float g_dt   [LL * DDI];
__device__ float g_tsbc [LL * 160];       // split-K accum: ts(128) | B(16) | C(16)
__device__ float g_y    [LL * DDI];
// tf32-rounded GEMM operands
__device__ float g_xr   [LL * HH];
__device__ float g_w12  [2 * DDI * HH];
__device__ float g_wout [HH * DDI];
__device__ float g_wdtbc[160 * DDI];
__device__ float g_wdtp [DDI * RR];

// ---------------- helpers ----------------
__device__ __forceinline__ uint32_t smem_u32(const void* p) {
    uint32_t a;
    asm("{ .reg .u64 t; cvta.to.shared.u64 t, %1; cvt.u32.u64 %0, t; }" : "=r"(a) : "l"(p));
    return a;
}
__device__ __forceinline__ void cp_async16(uint32_t dst, const void* src, bool pred) {
    int bytes = pred ? 16 : 0;
    asm volatile("cp.async.cg.shared.global [%0], [%1], 16, %2;" :: "r"(dst), "l"(src), "r"(bytes));
}
#define CP_COMMIT() asm volatile("cp.async.commit_group;" ::: "memory")
#define CP_WAIT1()  asm volatile("cp.async.wait_group 1;" ::: "memory")
#define CP_WAIT0()  asm volatile("cp.async.wait_group 0;" ::: "memory")

__device__ __forceinline__ float softplusf(float x) {
    return (x > 20.f) ? x : log1pf(expf(x));
}
__device__ __forceinline__ float rtf32(float x) {
    uint32_t u;
    asm("cvt.rna.tf32.f32 %0, %1;" : "=r"(u) : "f"(x));
    return __uint_as_float(u);
}
__device__ __forceinline__ void mma_tf32(float* c, const uint32_t* a, const uint32_t* b) {
    asm volatile(
        "mma.sync.aligned.m16n8k8.row.col.f32.tf32.tf32.f32 "
        "{%0,%1,%2,%3}, {%4,%5,%6,%7}, {%8,%9}, {%0,%1,%2,%3};"
        : "+f"(c[0]), "+f"(c[1]), "+f"(c[2]), "+f"(c[3])
        : "r"(a[0]), "r"(a[1]), "r"(a[2]), "r"(a[3]), "r"(b[0]), "r"(b[1]));
}
#define LDSM_X4(r0, r1, r2, r3, addr) \
    asm volatile("ldmatrix.sync.aligned.m8n8.x4.shared.b16 {%0,%1,%2,%3}, [%4];" \
                 : "=r"(r0), "=r"(r1), "=r"(r2), "=r"(r3) : "r"(addr))

// ---------------- tf32 mma.sync GEMM: C[M,N] = A[M,K] . B[N,K]^T ----------------
// CTA tile 128x256, warp tile 64x64 (8 warps 2x4), BK=32, 3-stage cp.async.
// EPI: 0 plain, 1 softplus(acc+bias[n]), 3 atomicAdd (split-K over gridDim.z)
#define BM 128
#define BN 256
#define TROWS (BM + BN)               // 384
#define SAPAD 36
#define STAGE_F (TROWS * SAPAD)       // 13824 floats
#define STAGE_BYTES (STAGE_F * 4)     // 55296 bytes
#define NSTAGE 3

template<int EPI>
__global__ __launch_bounds__(256) void gemm_mma(
    const float* __restrict__ A, const float* __restrict__ B, float* __restrict__ C,
    const float* __restrict__ bias, int M, int N, int K, int ldc)
{
    extern __shared__ float smem[];
    const int tid = threadIdx.x;
    const int wid = tid >> 5;
    const int lane = tid & 31;
    const int m0 = blockIdx.y * BM;
    const int n0 = blockIdx.x * BN;
    const int Ksplit = K / gridDim.z;
    const int kbase = blockIdx.z * Ksplit;
    const int KT = Ksplit >> 5;

    const int wm = (wid >> 2) * 64;   // warp M offset (2 in M)
    const int wn = (wid & 3) * 64;    // warp N offset (4 in N)

    float acc[4][8][4];
#pragma unroll
    for (int i = 0; i < 4; i++)
#pragma unroll
        for (int j = 0; j < 8; j++)
#pragma unroll
            for (int r = 0; r < 4; r++) acc[i][j][r] = 0.f;

    const uint32_t smem_b = smem_u32(smem);

    // ldmatrix per-lane byte offsets (within a stage)
    uint32_t aoff[4], boff[4];
    {
        const int arow = lane & 15;
        const int acolw = (lane >> 4) * 4;
#pragma unroll
        for (int mt = 0; mt < 4; mt++)
            aoff[mt] = (uint32_t)(((wm + mt * 16 + arow) * SAPAD + acolw) * 4);
        // B x4: lanes 0-7 -> (n= wn+16p + r, khalf0), 8-15 -> khalf1,
        //       16-23 -> (n+8, khalf0), 24-31 -> (n+8, khalf1)
        const int bg = lane >> 3;
        const int br = lane & 7;
        const int nadd = (bg >> 1) * 8;
        const int khalf = bg & 1;
#pragma unroll
        for (int p = 0; p < 4; p++)
            boff[p] = (uint32_t)(((BM + wn + 16 * p + nadd + br) * SAPAD + khalf * 4) * 4);
    }

    auto load_tile = [&](int kt, int s) {
        const uint32_t a_s = smem_b + (uint32_t)(s * STAGE_BYTES);
        const uint32_t b_s = a_s + (uint32_t)(BM * SAPAD * 4);
        const int k0 = kbase + (kt << 5);
        const float* Ab = A + (size_t)m0 * K + k0;
        const float* Bb = B + (size_t)n0 * K + k0;
#pragma unroll
        for (int i = 0; i < 4; i++) {           // 128 rows x 8 chunks
            int idx = tid + i * 256;
            int row = idx >> 3;
            int ch = (idx & 7) << 2;
            cp_async16(a_s + (uint32_t)(row * SAPAD + ch) * 4u, Ab + (size_t)row * K + ch, true);
        }
#pragma unroll
        for (int i = 0; i < 8; i++) {           // 256 rows x 8 chunks
            int idx = tid + i * 256;
            int row = idx >> 3;
            int ch = (idx & 7) << 2;
            cp_async16(b_s + (uint32_t)(row * SAPAD + ch) * 4u, Bb + (size_t)row * K + ch,
                       (n0 + row) < N);
        }
        CP_COMMIT();
    };

    load_tile(0, 0);
    if (KT > 1) load_tile(1, 1); else CP_COMMIT();

    for (int kt = 0; kt < KT; kt++) {
        if (kt == KT - 1) { CP_WAIT0(); } else { CP_WAIT1(); }
        __syncthreads();
        if (kt + 2 < KT) load_tile(kt + 2, (kt + 2) % NSTAGE);

        const uint32_t stage = smem_b + (uint32_t)((kt % NSTAGE) * STAGE_BYTES);
#pragma unroll
        for (int ks = 0; ks < 4; ks++) {
            uint32_t af[4][4], bf[8][2];
#pragma unroll
            for (int mt = 0; mt < 4; mt++)
                LDSM_X4(af[mt][0], af[mt][1], af[mt][2], af[mt][3],
                        stage + aoff[mt] + (uint32_t)(ks * 32));
#pragma unroll
            for (int p = 0; p < 4; p++)
                LDSM_X4(bf[2 * p][0], bf[2 * p][1], bf[2 * p + 1][0], bf[2 * p + 1][1],
                        stage + boff[p] + (uint32_t)(ks * 32));
#pragma unroll
            for (int mt = 0; mt < 4; mt++)
#pragma unroll
                for (int nt = 0; nt < 8; nt++)
                    mma_tf32(acc[mt][nt], af[mt], bf[nt]);
        }
    }

    // epilogue
    const int ar = lane >> 2;
    const int ac = lane & 3;
#pragma unroll
    for (int mt = 0; mt < 4; mt++) {
#pragma unroll
        for (int nt = 0; nt < 8; nt++) {
            int row = m0 + wm + mt * 16 + ar;
            int col = n0 + wn + nt * 8 + ac * 2;
            if (col >= N) continue;
            float* c0 = C + (size_t)row * ldc + col;
            float* c1 = C + (size_t)(row + 8) * ldc + col;
            float v0 = acc[mt][nt][0], v1 = acc[mt][nt][1];
            float v2 = acc[mt][nt][2], v3 = acc[mt][nt][3];
            if (EPI == 1) {
                float b0 = bias[col], b1 = bias[col + 1];
                v0 = softplusf(v0 + b0); v1 = softplusf(v1 + b1);
                v2 = softplusf(v2 + b0); v3 = softplusf(v3 + b1);
            }
            if (EPI == 3) {
                atomicAdd(c0, v0); atomicAdd(c0 + 1, v1);
                atomicAdd(c1, v2); atomicAdd(c1 + 1, v3);
            } else {
                *(float2*)c0 = make_float2(v0, v1);
                *(float2*)c1 = make_float2(v2, v3);
            }
        }
    }
}

// ---------------- small kernels ----------------
__global__ void round_copy(const float4* __restrict__ in, float4* __restrict__ out, int n4) {
    int i = blockIdx.x * blockDim.x + threadIdx.x;
    if (i < n4) {
        float4 v = in[i];
        v.x = rtf32(v.x); v.y = rtf32(v.y); v.z = rtf32(v.z); v.w = rtf32(v.w);
        out[i] = v;
    }
}
// fused round-copy for the small weights
__global__ void rc_small(const float4* __restrict__ wdtp_in, const float4* __restrict__ wdt_in,
                         const float4* __restrict__ wb_in, const float4* __restrict__ wc_in) {
    const int N_WDTP = (DDI * RR) / 4;        // 131072
    const int N_WDT  = (RR * DDI) / 4;        // 131072
    const int N_W16  = (NSS * DDI) / 4;       // 16384
    int i = blockIdx.x * blockDim.x + threadIdx.x;
    const float4* src;
    float4* dst;
    if (i < N_WDTP) { src = wdtp_in + i; dst = (float4*)g_wdtp + i; }
    else if (i < N_WDTP + N_WDT) { int j = i - N_WDTP; src = wdt_in + j; dst = (float4*)g_wdtbc + j; }
    else if (i < N_WDTP + N_WDT + N_W16) { int j = i - N_WDTP - N_WDT; src = wb_in + j; dst = (float4*)(g_wdtbc + (size_t)RR * DDI) + j; }
    else if (i < N_WDTP + N_WDT + 2 * N_W16) { int j = i - N_WDTP - N_WDT - N_W16; src = wc_in + j; dst = (float4*)(g_wdtbc + (size_t)(RR + NSS) * DDI) + j; }
    else return;
    float4 v = *src;
    v.x = rtf32(v.x); v.y = rtf32(v.y); v.z = rtf32(v.z); v.w = rtf32(v.w);
    *dst = v;
}
__global__ void zero_kernel(float* __restrict__ p, int n) {
    int i = blockIdx.x * blockDim.x + threadIdx.x;
    if (i < n) p[i] = 0.f;
}
__global__ void round_ts_kernel() {
    int i = blockIdx.x * blockDim.x + threadIdx.x;
    int l = i >> 7, r = i & 127;
    g_ts[i] = rtf32(g_tsbc[l * 160 + r]);
}

// conv (K=4, causal) + SiLU
__global__ void conv_silu_kernel(const float* __restrict__ cw, const float* __restrict__ cb) {
    int idx = blockIdx.x * blockDim.x + threadIdx.x;
    int l = idx >> 12;
    int d = idx & (DDI - 1);
    float4 w = ((const float4*)cw)[d];
    float acc = cb[d];
    const float* hp = g_pg + d;
    if (l >= 3) acc = fmaf(w.x, hp[(size_t)(l - 3) * 8192], acc);
    if (l >= 2) acc = fmaf(w.y, hp[(size_t)(l - 2) * 8192], acc);
    if (l >= 1) acc = fmaf(w.z, hp[(size_t)(l - 1) * 8192], acc);
    acc = fmaf(w.w, hp[(size_t)l * 8192], acc);
    float s = acc / (1.f + __expf(-acc));
    g_hs[idx] = rtf32(s);
}

// selective scan
__global__ void scan_kernel(const float* __restrict__ A_log, const float* __restrict__ Dv) {
    int gwarp = (blockIdx.x * blockDim.x + threadIdx.x) >> 5;
    int lane = threadIdx.x & 31;
    int c = lane >> 4;
    int n = lane & 15;
    int d = gwarp * 2 + c;

    const float Acoef = -__expf(A_log[d * NSS + n]);
    const float Dd = Dv[d];
    float s = 0.f;
#pragma unroll 2
    for (int l = 0; l < LL; l++) {
        float dtv = g_dt[(size_t)l * DDI + d];
        float hsv = g_hs[(size_t)l * DDI + d];
        float Bv = g_tsbc[l * 160 + 128 + n];
        float Cv = g_tsbc[l * 160 + 144 + n];
        float a = __expf(Acoef * dtv);
        s = fmaf(a, s, dtv * Bv * hsv);
        float v = s * Cv;
        v += __shfl_xor_sync(0xFFFFFFFFu, v, 1);
        v += __shfl_xor_sync(0xFFFFFFFFu, v, 2);
        v += __shfl_xor_sync(0xFFFFFFFFu, v, 4);
        v += __shfl_xor_sync(0xFFFFFFFFu, v, 8);
        if (n == 0) {
            float gv = g_pg[(size_t)l * 8192 + 4096 + d];
            float y = (v + hsv * Dd) * (gv / (1.f + __expf(-gv)));
            g_y[(size_t)l * DDI + d] = rtf32(y);
        }
    }
}

// ---------------- host ----------------
extern "C" void kernel_launch(void* const* d_in, const int* in_sizes, int n_in,
                              void* d_out, int out_size)
{
    const float* x           = (const float*)d_in[0];
    const float* W_in_states = (const float*)d_in[1];
    const float* W_in_gates  = (const float*)d_in[2];
    const float* conv_w      = (const float*)d_in[3];
    const float* conv_b      = (const float*)d_in[4];
    const float* W_dt        = (const float*)d_in[5];
    const float* W_b         = (const float*)d_in[6];
    const float* W_c         = (const float*)d_in[7];
    const float* W_dtproj    = (const float*)d_in[8];
    const float* b_dtproj    = (const float*)d_in[9];
    const float* A_log       = (const float*)d_in[10];
    const float* Dv          = (const float*)d_in[11];
    const float* W_out       = (const float*)d_in[12];
    float* out = (float*)d_out;

    float *pg, *hs, *ts, *dt, *tsbc, *y, *xr, *w12, *wout, *wdtbc, *wdtp;
    cudaGetSymbolAddress((void**)&pg,    g_pg);
    cudaGetSymbolAddress((void**)&hs,    g_hs);
    cudaGetSymbolAddress((void**)&ts,    g_ts);
    cudaGetSymbolAddress((void**)&dt,    g_dt);
    cudaGetSymbolAddress((void**)&tsbc,  g_tsbc);
    cudaGetSymbolAddress((void**)&y,     g_y);
    cudaGetSymbolAddress((void**)&xr,    g_xr);
    cudaGetSymbolAddress((void**)&w12,   g_w12);
    cudaGetSymbolAddress((void**)&wout,  g_wout);
    cudaGetSymbolAddress((void**)&wdtbc, g_wdtbc);
    cudaGetSymbolAddress((void**)&wdtp,  g_wdtp);

    const int SMEM = NSTAGE * STAGE_BYTES;   // 165888 bytes
    cudaFuncSetAttribute(gemm_mma<0>, cudaFuncAttributeMaxDynamicSharedMemorySize, SMEM);
    cudaFuncSetAttribute(gemm_mma<1>, cudaFuncAttributeMaxDynamicSharedMemorySize, SMEM);
    cudaFuncSetAttribute(gemm_mma<3>, cudaFuncAttributeMaxDynamicSharedMemorySize, SMEM);

    auto rc = [&](const float* src, float* dst, int n) {
        int n4 = n / 4;
        round_copy<<<(n4 + 255) / 256, 256>>>((const float4*)src, (float4*)dst, n4);
    };
    // launches 0-4 (profiled launch index 5 = G12 GEMM)
    rc(x, xr, LL * HH);
    rc(W_in_states, w12, DDI * HH);
    rc(W_in_gates,  w12 + (size_t)DDI * HH, DDI * HH);
    rc(W_out, wout, HH * DDI);
    {
        int total4 = (DDI * RR + RR * DDI + 2 * NSS * DDI) / 4;
        rc_small<<<(total4 + 255) / 256, 256>>>((const float4*)W_dtproj, (const float4*)W_dt,
                                                (const float4*)W_b, (const float4*)W_c);
    }

    // G12 (launch 5): pg[L, 8192] = x . [W_in_states; W_in_gates]^T
    gemm_mma<0><<<dim3(2 * DDI / BN, LL / BM), 256, SMEM>>>(xr, w12, pg, nullptr, LL, 2 * DDI, HH, 2 * DDI);
    // conv + silu -> hs
    conv_silu_kernel<<<(LL * DDI) / 256, 256>>>(conv_w, conv_b);
    // zero split-K accumulator
    zero_kernel<<<(LL * 160 + 255) / 256, 256>>>(tsbc, LL * 160);
    // G35 (split-K=8, atomic): tsbc[L, 160] = hs . [W_dt; W_b; W_c]^T
    gemm_mma<3><<<dim3(1, LL / BM, 8), 256, SMEM>>>(hs, wdtbc, tsbc, nullptr, LL, 160, DDI, 160);
    // round ts slice
    round_ts_kernel<<<(LL * RR) / 256, 256>>>();
    // G4: dt = softplus(ts . W_dtproj^T + b)
    gemm_mma<1><<<dim3(DDI / BN, LL / BM), 256, SMEM>>>(ts, wdtp, dt, b_dtproj, LL, DDI, RR, DDI);
    // scan + gating -> y
    scan_kernel<<<(DDI / 2 * 32) / 256, 256>>>(A_log, Dv);
    // zero output, then G6 (split-K=2, atomic): out = y . W_out^T
    zero_kernel<<<(LL * HH + 255) / 256, 256>>>(out, LL * HH);
    gemm_mma<3><<<dim3(HH / BN, LL / BM, 2), 256, SMEM>>>(y, wout, out, nullptr, LL, HH, DDI, HH);
}

// round 8
// speedup vs baseline: 4.3048x; 1.2392x over previous
#include <cuda_runtime.h>
#include <cuda_fp16.h>
#include <cstdint>

#define LL 1024
#define HH 2048
#define DDI 4096
#define NSS 16
#define RR 128

// ---------------- scratch ----------------
__device__ float  g_pg   [LL * 2 * DDI];   // [l,0:4096]=hs_pre, [l,4096:8192]=gate (fp32)
__device__ __half g_hsh  [LL * DDI];       // conv+silu output (half, GEMM A + scan)
__device__ __half g_tsh  [LL * RR];        // rounded time_step (half)
__device__ float  g_dt   [LL * DDI];       // softplus dt (fp32, scan only)
__device__ float  g_tsbc [LL * 160];       // split-K accum: ts(128)|B(16)|C(16) fp32
__device__ __half g_yh   [LL * DDI];       // gated ssm out (half, GEMM A)
// half operand copies
__device__ __half g_xh   [LL * HH];
__device__ __half g_w12h [2 * DDI * HH];
__device__ __half g_wouth[HH * DDI];
__device__ __half g_wdtbch[160 * DDI];
__device__ __half g_wdtph [DDI * RR];

// ---------------- helpers ----------------
__device__ __forceinline__ uint32_t smem_u32(const void* p) {
    uint32_t a;
    asm("{ .reg .u64 t; cvta.to.shared.u64 t, %1; cvt.u32.u64 %0, t; }" : "=r"(a) : "l"(p));
    return a;
}
__device__ __forceinline__ void cp_async16(uint32_t dst, const void* src, bool pred) {
    int bytes = pred ? 16 : 0;
    asm volatile("cp.async.cg.shared.global [%0], [%1], 16, %2;" :: "r"(dst), "l"(src), "r"(bytes));
}
#define CP_COMMIT() asm volatile("cp.async.commit_group;" ::: "memory")
#define CP_WAIT1()  asm volatile("cp.async.wait_group 1;" ::: "memory")
#define CP_WAIT0()  asm volatile("cp.async.wait_group 0;" ::: "memory")

__device__ __forceinline__ float softplusf(float x) {
    return (x > 20.f) ? x : log1pf(expf(x));
}
__device__ __forceinline__ void mma_f16(float* c, const uint32_t* a, const uint32_t* b) {
    asm volatile(
        "mma.sync.aligned.m16n8k16.row.col.f32.f16.f16.f32 "
        "{%0,%1,%2,%3}, {%4,%5,%6,%7}, {%8,%9}, {%0,%1,%2,%3};"
        : "+f"(c[0]), "+f"(c[1]), "+f"(c[2]), "+f"(c[3])
        : "r"(a[0]), "r"(a[1]), "r"(a[2]), "r"(a[3]), "r"(b[0]), "r"(b[1]));
}
#define LDSM_X4(r0, r1, r2, r3, addr) \
    asm volatile("ldmatrix.sync.aligned.m8n8.x4.shared.b16 {%0,%1,%2,%3}, [%4];" \
                 : "=r"(r0), "=r"(r1), "=r"(r2), "=r"(r3) : "r"(addr))

// ---------------- fp16 mma.sync GEMM: C[M,N] = A[M,K] . B[N,K]^T ----------------
// CTA tile 128x256, warp tile 64x64 (8 warps 2x4), BK=64 halfs, 3-stage cp.async.
// EPI: 0 plain fp32 store, 1 softplus(acc+bias[n]), 3 atomicAdd (split-K over gridDim.z)
#define BM 128
#define BN 256
#define TROWS (BM + BN)                 // 384
#define SAPADH 72                        // halfs per row (144B, 16B-aligned, conflict-free)
#define STAGE_BYTES (TROWS * SAPADH * 2) // 55296
#define NSTAGE 3

template<int EPI>
__global__ __launch_bounds__(256, 1) void gemm_mma(
    const __half* __restrict__ A, const __half* __restrict__ B, float* __restrict__ C,
    const float* __restrict__ bias, int M, int N, int K, int ldc)
{
    extern __shared__ __half smem[];
    const int tid = threadIdx.x;
    const int wid = tid >> 5;
    const int lane = tid & 31;
    const int m0 = blockIdx.y * BM;
    const int n0 = blockIdx.x * BN;
    const int Ksplit = K / gridDim.z;
    const int kbase = blockIdx.z * Ksplit;
    const int KT = Ksplit >> 6;          // BK = 64

    const int wm = (wid >> 2) * 64;
    const int wn = (wid & 3) * 64;

    float acc[4][8][4];
#pragma unroll
    for (int i = 0; i < 4; i++)
#pragma unroll
        for (int j = 0; j < 8; j++)
#pragma unroll
            for (int r = 0; r < 4; r++) acc[i][j][r] = 0.f;

    const uint32_t smem_b = smem_u32(smem);

    // ldmatrix per-lane byte offsets (within a stage)
    uint32_t aoff[4], boff[4];
    {
        const int arow = lane & 15;
        const int acolh = (lane >> 4) * 8;      // halfs
#pragma unroll
        for (int mt = 0; mt < 4; mt++)
            aoff[mt] = (uint32_t)(((wm + mt * 16 + arow) * SAPADH + acolh) * 2);
        const int bg = lane >> 3;
        const int br = lane & 7;
        const int nadd = (bg >> 1) * 8;
        const int khalf = (bg & 1) * 8;         // halfs
#pragma unroll
        for (int p = 0; p < 4; p++)
            boff[p] = (uint32_t)(((BM + wn + 16 * p + nadd + br) * SAPADH + khalf) * 2);
    }

    auto load_tile = [&](int kt, int s) {
        const uint32_t a_s = smem_b + (uint32_t)(s * STAGE_BYTES);
        const uint32_t b_s = a_s + (uint32_t)(BM * SAPADH * 2);
        const int k0 = kbase + (kt << 6);
        const __half* Ab = A + (size_t)m0 * K + k0;
        const __half* Bb = B + (size_t)n0 * K + k0;
#pragma unroll
        for (int i = 0; i < 4; i++) {           // 128 rows x 8 chunks (16B = 8 halfs)
            int idx = tid + i * 256;
            int row = idx >> 3;
            int ch = (idx & 7) << 3;
            cp_async16(a_s + (uint32_t)(row * SAPADH + ch) * 2u, Ab + (size_t)row * K + ch, true);
        }
#pragma unroll
        for (int i = 0; i < 8; i++) {           // 256 rows x 8 chunks
            int idx = tid + i * 256;
            int row = idx >> 3;
            int ch = (idx & 7) << 3;
            cp_async16(b_s + (uint32_t)(row * SAPADH + ch) * 2u, Bb + (size_t)row * K + ch,
                       (n0 + row) < N);
        }
        CP_COMMIT();
    };

    load_tile(0, 0);
    if (KT > 1) load_tile(1, 1); else CP_COMMIT();

    for (int kt = 0; kt < KT; kt++) {
        if (kt == KT - 1) { CP_WAIT0(); } else { CP_WAIT1(); }
        __syncthreads();
        if (kt + 2 < KT) load_tile(kt + 2, (kt + 2) % NSTAGE);

        const uint32_t stage = smem_b + (uint32_t)((kt % NSTAGE) * STAGE_BYTES);
#pragma unroll
        for (int ks = 0; ks < 4; ks++) {        // 4 x k16
            uint32_t af[4][4], bf[8][2];
#pragma unroll
            for (int mt = 0; mt < 4; mt++)
                LDSM_X4(af[mt][0], af[mt][1], af[mt][2], af[mt][3],
                        stage + aoff[mt] + (uint32_t)(ks * 32));
#pragma unroll
            for (int p = 0; p < 4; p++)
                LDSM_X4(bf[2 * p][0], bf[2 * p][1], bf[2 * p + 1][0], bf[2 * p + 1][1],
                        stage + boff[p] + (uint32_t)(ks * 32));
#pragma unroll
            for (int mt = 0; mt < 4; mt++)
#pragma unroll
                for (int nt = 0; nt < 8; nt++)
                    mma_f16(acc[mt][nt], af[mt], bf[nt]);
        }
    }

    // epilogue
    const int ar = lane >> 2;
    const int ac = lane & 3;
#pragma unroll
    for (int mt = 0; mt < 4; mt++) {
#pragma unroll
        for (int nt = 0; nt < 8; nt++) {
            int row = m0 + wm + mt * 16 + ar;
            int col = n0 + wn + nt * 8 + ac * 2;
            if (col >= N) continue;
            float* c0 = C + (size_t)row * ldc + col;
            float* c1 = C + (size_t)(row + 8) * ldc + col;
            float v0 = acc[mt][nt][0], v1 = acc[mt][nt][1];
            float v2 = acc[mt][nt][2], v3 = acc[mt][nt][3];
            if (EPI == 1) {
                float b0 = bias[col], b1 = bias[col + 1];
                v0 = softplusf(v0 + b0); v1 = softplusf(v1 + b1);
                v2 = softplusf(v2 + b0); v3 = softplusf(v3 + b1);
            }
            if (EPI == 3) {
                atomicAdd(c0, v0); atomicAdd(c0 + 1, v1);
                atomicAdd(c1, v2); atomicAdd(c1 + 1, v3);
            } else {
                *(float2*)c0 = make_float2(v0, v1);
                *(float2*)c1 = make_float2(v2, v3);
            }
        }
    }
}

// ---------------- conversion kernels ----------------
__device__ __forceinline__ uint32_t pack_h2(float a, float b) {
    __half2 h = __floats2half2_rn(a, b);
    return *reinterpret_cast<uint32_t*>(&h);
}
__global__ void cvt_half(const float4* __restrict__ in, uint2* __restrict__ out, int n4) {
    int i = blockIdx.x * blockDim.x + threadIdx.x;
    if (i < n4) {
        float4 v = in[i];
        uint2 u;
        u.x = pack_h2(v.x, v.y);
        u.y = pack_h2(v.z, v.w);
        out[i] = u;
    }
}
__global__ void cvt_small(const float4* __restrict__ wdtp_in, const float4* __restrict__ wdt_in,
                          const float4* __restrict__ wb_in, const float4* __restrict__ wc_in) {
    const int N_WDTP = (DDI * RR) / 4;
    const int N_WDT  = (RR * DDI) / 4;
    const int N_W16  = (NSS * DDI) / 4;
    int i = blockIdx.x * blockDim.x + threadIdx.x;
    const float4* src;
    uint2* dst;
    if (i < N_WDTP) { src = wdtp_in + i; dst = (uint2*)g_wdtph + i; }
    else if (i < N_WDTP + N_WDT) { int j = i - N_WDTP; src = wdt_in + j; dst = (uint2*)g_wdtbch + j; }
    else if (i < N_WDTP + N_WDT + N_W16) { int j = i - N_WDTP - N_WDT; src = wb_in + j; dst = (uint2*)(g_wdtbch + (size_t)RR * DDI) + j; }
    else if (i < N_WDTP + N_WDT + 2 * N_W16) { int j = i - N_WDTP - N_WDT - N_W16; src = wc_in + j; dst = (uint2*)(g_wdtbch + (size_t)(RR + NSS) * DDI) + j; }
    else return;
    float4 v = *src;
    uint2 u;
    u.x = pack_h2(v.x, v.y);
    u.y = pack_h2(v.z, v.w);
    *dst = u;
}
__global__ void zero_kernel(float* __restrict__ p, int n) {
    int i = blockIdx.x * blockDim.x + threadIdx.x;
    if (i < n) p[i] = 0.f;
}
__global__ void round_ts_kernel() {
    int i = blockIdx.x * blockDim.x + threadIdx.x;
    int l = i >> 7, r = i & 127;
    g_tsh[i] = __float2half_rn(g_tsbc[l * 160 + r]);
}

// conv (K=4, causal) + SiLU -> half
__global__ void conv_silu_kernel(const float* __restrict__ cw, const float* __restrict__ cb) {
    int idx = blockIdx.x * blockDim.x + threadIdx.x;
    int l = idx >> 12;
    int d = idx & (DDI - 1);
    float4 w = ((const float4*)cw)[d];
    float acc = cb[d];
    const float* hp = g_pg + d;
    if (l >= 3) acc = fmaf(w.x, hp[(size_t)(l - 3) * 8192], acc);
    if (l >= 2) acc = fmaf(w.y, hp[(size_t)(l - 2) * 8192], acc);
    if (l >= 1) acc = fmaf(w.z, hp[(size_t)(l - 1) * 8192], acc);
    acc = fmaf(w.w, hp[(size_t)l * 8192], acc);
    float s = acc / (1.f + __expf(-acc));
    g_hsh[idx] = __float2half_rn(s);
}

// selective scan: warp = 2 channels, lane = state n
__global__ void scan_kernel(const float* __restrict__ A_log, const float* __restrict__ Dv) {
    int gwarp = (blockIdx.x * blockDim.x + threadIdx.x) >> 5;
    int lane = threadIdx.x & 31;
    int c = lane >> 4;
    int n = lane & 15;
    int d = gwarp * 2 + c;

    const float Acoef = -__expf(A_log[d * NSS + n]);
    const float Dd = Dv[d];
    float s = 0.f;
#pragma unroll 2
    for (int l = 0; l < LL; l++) {
        float dtv = g_dt[(size_t)l * DDI + d];
        float hsv = __half2float(g_hsh[(size_t)l * DDI + d]);
        float Bv = g_tsbc[l * 160 + 128 + n];
        float Cv = g_tsbc[l * 160 + 144 + n];
        float a = __expf(Acoef * dtv);
        s = fmaf(a, s, dtv * Bv * hsv);
        float v = s * Cv;
        v += __shfl_xor_sync(0xFFFFFFFFu, v, 1);
        v += __shfl_xor_sync(0xFFFFFFFFu, v, 2);
        v += __shfl_xor_sync(0xFFFFFFFFu, v, 4);
        v += __shfl_xor_sync(0xFFFFFFFFu, v, 8);
        if (n == 0) {
            float gv = g_pg[(size_t)l * 8192 + 4096 + d];
            float y = (v + hsv * Dd) * (gv / (1.f + __expf(-gv)));
            g_yh[(size_t)l * DDI + d] = __float2half_rn(y);
        }
    }
}

// ---------------- host ----------------
extern "C" void kernel_launch(void* const* d_in, const int* in_sizes, int n_in,
                              void* d_out, int out_size)
{
    const float* x           = (const float*)d_in[0];
    const float* W_in_states = (const float*)d_in[1];
    const float* W_in_gates  = (const float*)d_in[2];
    const float* conv_w      = (const float*)d_in[3];
    const float* conv_b      = (const float*)d_in[4];
    const float* W_dt        = (const float*)d_in[5];
    const float* W_b         = (const float*)d_in[6];
    const float* W_c         = (const float*)d_in[7];
    const float* W_dtproj    = (const float*)d_in[8];
    const float* b_dtproj    = (const float*)d_in[9];
    const float* A_log       = (const float*)d_in[10];
    const float* Dv          = (const float*)d_in[11];
    const float* W_out       = (const float*)d_in[12];
    float* out = (float*)d_out;

    float *pg, *dt, *tsbc;
    __half *hsh, *tsh, *yh, *xh, *w12h, *wouth, *wdtbch, *wdtph;
    cudaGetSymbolAddress((void**)&pg,     g_pg);
    cudaGetSymbolAddress((void**)&dt,     g_dt);
    cudaGetSymbolAddress((void**)&tsbc,   g_tsbc);
    cudaGetSymbolAddress((void**)&hsh,    g_hsh);
    cudaGetSymbolAddress((void**)&tsh,    g_tsh);
    cudaGetSymbolAddress((void**)&yh,     g_yh);
    cudaGetSymbolAddress((void**)&xh,     g_xh);
    cudaGetSymbolAddress((void**)&w12h,   g_w12h);
    cudaGetSymbolAddress((void**)&wouth,  g_wouth);
    cudaGetSymbolAddress((void**)&wdtbch, g_wdtbch);
    cudaGetSymbolAddress((void**)&wdtph,  g_wdtph);

    const int SMEM = NSTAGE * STAGE_BYTES;   // 165888 bytes
    cudaFuncSetAttribute(gemm_mma<0>, cudaFuncAttributeMaxDynamicSharedMemorySize, SMEM);
    cudaFuncSetAttribute(gemm_mma<1>, cudaFuncAttributeMaxDynamicSharedMemorySize, SMEM);
    cudaFuncSetAttribute(gemm_mma<3>, cudaFuncAttributeMaxDynamicSharedMemorySize, SMEM);

    auto cv = [&](const float* src, __half* dst, int n) {
        int n4 = n / 4;
        cvt_half<<<(n4 + 255) / 256, 256>>>((const float4*)src, (uint2*)dst, n4);
    };
    cv(x, xh, LL * HH);
    cv(W_in_states, w12h, DDI * HH);
    cv(W_in_gates,  w12h + (size_t)DDI * HH, DDI * HH);
    cv(W_out, wouth, HH * DDI);
    {
        int total4 = (DDI * RR + RR * DDI + 2 * NSS * DDI) / 4;
        cvt_small<<<(total4 + 255) / 256, 256>>>((const float4*)W_dtproj, (const float4*)W_dt,
                                                 (const float4*)W_b, (const float4*)W_c);
    }

    // G12: pg[L, 8192] = x . [W_in_states; W_in_gates]^T  (fp32 out)
    gemm_mma<0><<<dim3(2 * DDI / BN, LL / BM), 256, SMEM>>>(xh, w12h, pg, nullptr, LL, 2 * DDI, HH, 2 * DDI);
    // conv + silu -> hsh
    conv_silu_kernel<<<(LL * DDI) / 256, 256>>>(conv_w, conv_b);
    // zero split-K accumulator
    zero_kernel<<<(LL * 160 + 255) / 256, 256>>>(tsbc, LL * 160);
    // G35 (split-K=8, atomic): tsbc[L, 160] = hs . [W_dt; W_b; W_c]^T
    gemm_mma<3><<<dim3(1, LL / BM, 8), 256, SMEM>>>(hsh, wdtbch, tsbc, nullptr, LL, 160, DDI, 160);
    // round ts slice -> half
    round_ts_kernel<<<(LL * RR) / 256, 256>>>();
    // G4: dt[L, DI] = softplus(ts . W_dtproj^T + b)
    gemm_mma<1><<<dim3(DDI / BN, LL / BM), 256, SMEM>>>(tsh, wdtph, dt, b_dtproj, LL, DDI, RR, DDI);
    // scan + gating -> yh
    scan_kernel<<<(DDI / 2 * 32) / 256, 256>>>(A_log, Dv);
    // zero output, then G6 (split-K=2, atomic): out = y . W_out^T
    zero_kernel<<<(LL * HH + 255) / 256, 256>>>(out, LL * HH);
    gemm_mma<3><<<dim3(HH / BN, LL / BM, 2), 256, SMEM>>>(yh, wouth, out, nullptr, LL, HH, DDI, HH);
}